// round 16
// baseline (speedup 1.0000x reference)
#include <cuda_runtime.h>
#include <cuda_fp16.h>
#include <cstdint>

#define HDIM 64
#define BN_EPS 1e-5f
#define MAXN 131072
#define MAXL 4

// Scratch (device globals — no allocation allowed). 16B-aligned.
__device__ __align__(16) __half g_y16[MAXN * HDIM]; // y = h @ Wa (fp16 gather)
__device__ __align__(16) float g_z[MAXN * HDIM];    // z = (1+eps)*y + scatter
__device__ __align__(16) float g_h2[MAXN * HDIM];   // pre-BN output of MLP
__device__ __align__(16) float g_h[MAXN * HDIM];    // residual stream
__device__ __align__(16) float g_sum[MAXL][HDIM];   // per-layer BN stats
__device__ __align__(16) float g_sumsq[MAXL][HDIM];

// tf32 helpers
#define TF32(u, f) asm("cvt.rna.tf32.f32 %0, %1;" : "=r"(u) : "f"(f))
#define MMA_TF32(d, a0, a1, a2, a3, b0, b1) \
    asm volatile("mma.sync.aligned.m16n8k8.row.col.f32.tf32.tf32.f32 " \
        "{%0,%1,%2,%3}, {%4,%5,%6,%7}, {%8,%9}, {%0,%1,%2,%3};" \
        : "+f"(d[0]), "+f"(d[1]), "+f"(d[2]), "+f"(d[3]) \
        : "r"(a0), "r"(a1), "r"(a2), "r"(a3), "r"(b0), "r"(b1))

#define WPAD 72    // Ws row stride (conflict-free B-frag loads)
#define APAD 132   // AsT row stride (BM + 4)

// Dynamic smem sizes (bytes)
#define DYN_K64  ((64 * WPAD + 64 * APAD) * 4)    // 52224
#define DYN_K128 ((128 * WPAD + 128 * APAD) * 4)  // 104448

// ===========================================================================
// GEMM A (tf32 MMA, K=64, FUSE): single-phase staging (whole A-tile + W),
// one barrier, then uninterrupted 8-step MMA loop. Dynamic smem 52 KB.
// y16 = A' @ W (fp16), z = (1+eps)*(A' @ W) (fp32).
// A' = [residual +] relu(BN(h2)) on the fly, written to hbuf (fp32).
// ===========================================================================
__global__ __launch_bounds__(256) void gemm_a_mma_kernel(
    const float* __restrict__ A, const float* __restrict__ W,
    const float* __restrict__ eps_ptr, int eps_idx,
    const float* __restrict__ gamma, const float* __restrict__ beta,
    int stat_set, int residual, float invN,
    float* __restrict__ hbuf, __half* __restrict__ y16,
    float* __restrict__ z, int N)
{
    constexpr int K = 64, BM = 128;
    extern __shared__ __align__(16) float sm[];
    float* Ws  = sm;                 // [K][WPAD]
    float* AsT = sm + K * WPAD;      // [K][APAD]
    __shared__ __align__(16) float s_scale[HDIM], s_shift[HDIM];

    const int tid = threadIdx.x;
    const int lane = tid & 31, wid = tid >> 5;
    const int g = lane >> 2, tig = lane & 3;
    const int warpM = wid & 3, warpN = wid >> 2;
    const int r0 = blockIdx.x * BM;

    if (tid < HDIM) {
        float mean = g_sum[stat_set][tid] * invN;
        float var  = g_sumsq[stat_set][tid] * invN - mean * mean;
        float sc   = gamma[tid] * rsqrtf(var + BN_EPS);
        s_scale[tid] = sc;
        s_shift[tid] = beta[tid] - mean * sc;
    }
    __syncthreads();                 // s_scale/s_shift ready for FUSE math

    // Stage W (tf32-rounded)
    #pragma unroll
    for (int i = tid; i < K * 16; i += 256) {
        int row = i >> 4, c4 = (i & 15) * 4;
        float4 v = *(const float4*)(W + (size_t)row * HDIM + c4);
        uint32_t u0, u1, u2, u3;
        TF32(u0, v.x); TF32(u1, v.y); TF32(u2, v.z); TF32(u3, v.w);
        *(float4*)&Ws[row * WPAD + c4] =
            make_float4(__uint_as_float(u0), __uint_as_float(u1),
                        __uint_as_float(u2), __uint_as_float(u3));
    }

    // Stage full A-tile (FUSE: BN+ReLU[+residual], write-back to hbuf)
    #pragma unroll
    for (int pp = 0; pp < 8; pp++) {
        int row = (tid >> 4) + pp * 16;
        int c4 = (tid & 15) * 4;
        int gr = r0 + row;
        float4 v = make_float4(0.f, 0.f, 0.f, 0.f);
        if (gr < N) {
            v = *(const float4*)(A + (size_t)gr * K + c4);
            float4 sc = *(const float4*)&s_scale[c4];
            float4 sh = *(const float4*)&s_shift[c4];
            v.x = fmaxf(fmaf(v.x, sc.x, sh.x), 0.f);
            v.y = fmaxf(fmaf(v.y, sc.y, sh.y), 0.f);
            v.z = fmaxf(fmaf(v.z, sc.z, sh.z), 0.f);
            v.w = fmaxf(fmaf(v.w, sc.w, sh.w), 0.f);
            float* hp = hbuf + (size_t)gr * K + c4;
            if (residual) {
                float4 h = *(const float4*)hp;
                v.x += h.x; v.y += h.y; v.z += h.z; v.w += h.w;
            }
            *(float4*)hp = v;
        }
        uint32_t u0, u1, u2, u3;
        TF32(u0, v.x); TF32(u1, v.y); TF32(u2, v.z); TF32(u3, v.w);
        AsT[(c4 + 0) * APAD + row] = __uint_as_float(u0);
        AsT[(c4 + 1) * APAD + row] = __uint_as_float(u1);
        AsT[(c4 + 2) * APAD + row] = __uint_as_float(u2);
        AsT[(c4 + 3) * APAD + row] = __uint_as_float(u3);
    }
    __syncthreads();

    float acc[2][4][4];
    #pragma unroll
    for (int m = 0; m < 2; m++)
        #pragma unroll
        for (int j = 0; j < 4; j++)
            #pragma unroll
            for (int q = 0; q < 4; q++) acc[m][j][q] = 0.f;

    #pragma unroll
    for (int kc = 0; kc < K / 8; kc++) {
        const int kl = kc * 8;
        uint32_t bf[4][2];
        #pragma unroll
        for (int j = 0; j < 4; j++) {
            int n = warpN * 32 + j * 8 + g;
            bf[j][0] = __float_as_uint(Ws[(kl + tig) * WPAD + n]);
            bf[j][1] = __float_as_uint(Ws[(kl + tig + 4) * WPAD + n]);
        }
        #pragma unroll
        for (int m = 0; m < 2; m++) {
            int rb = warpM * 32 + m * 16;
            uint32_t a0 = __float_as_uint(AsT[(kl + tig) * APAD + rb + g]);
            uint32_t a1 = __float_as_uint(AsT[(kl + tig) * APAD + rb + g + 8]);
            uint32_t a2 = __float_as_uint(AsT[(kl + tig + 4) * APAD + rb + g]);
            uint32_t a3 = __float_as_uint(AsT[(kl + tig + 4) * APAD + rb + g + 8]);
            #pragma unroll
            for (int j = 0; j < 4; j++)
                MMA_TF32(acc[m][j], a0, a1, a2, a3, bf[j][0], bf[j][1]);
        }
    }

    const float ep = 1.0f + eps_ptr[eps_idx];
    #pragma unroll
    for (int m = 0; m < 2; m++) {
        #pragma unroll
        for (int half = 0; half < 2; half++) {
            int gr = r0 + warpM * 32 + m * 16 + g + half * 8;
            if (gr < N) {
                #pragma unroll
                for (int j = 0; j < 4; j++) {
                    int col = warpN * 32 + j * 8 + 2 * tig;
                    float v0 = acc[m][j][half * 2 + 0];
                    float v1 = acc[m][j][half * 2 + 1];
                    *(float2*)(z + (size_t)gr * HDIM + col) =
                        make_float2(v0 * ep, v1 * ep);
                    *(__half2*)(y16 + (size_t)gr * HDIM + col) =
                        __float22half2_rn(make_float2(v0, v1));
                }
            }
        }
    }
}

// ===========================================================================
// GEMM A layer-0 (tf32 MMA, K=128, no FUSE): single-phase, dyn smem 104 KB.
// Block 0 zeroes BN stat sets.
// ===========================================================================
__global__ __launch_bounds__(256) void gemm_a0_mma_kernel(
    const float* __restrict__ A, const float* __restrict__ W,
    const float* __restrict__ eps_ptr,
    __half* __restrict__ y16, float* __restrict__ z, int N)
{
    constexpr int K = 128, BM = 128;
    extern __shared__ __align__(16) float sm[];
    float* Ws  = sm;                 // [K][WPAD]
    float* AsT = sm + K * WPAD;      // [K][APAD]

    const int tid = threadIdx.x;
    const int lane = tid & 31, wid = tid >> 5;
    const int g = lane >> 2, tig = lane & 3;
    const int warpM = wid & 3, warpN = wid >> 2;
    const int r0 = blockIdx.x * BM;

    if (blockIdx.x == 0 && tid < HDIM) {
        #pragma unroll
        for (int s = 0; s < MAXL; s++) { g_sum[s][tid] = 0.f; g_sumsq[s][tid] = 0.f; }
    }

    #pragma unroll
    for (int i = tid; i < K * 16; i += 256) {
        int row = i >> 4, c4 = (i & 15) * 4;
        float4 v = *(const float4*)(W + (size_t)row * HDIM + c4);
        uint32_t u0, u1, u2, u3;
        TF32(u0, v.x); TF32(u1, v.y); TF32(u2, v.z); TF32(u3, v.w);
        *(float4*)&Ws[row * WPAD + c4] =
            make_float4(__uint_as_float(u0), __uint_as_float(u1),
                        __uint_as_float(u2), __uint_as_float(u3));
    }

    #pragma unroll
    for (int pp = 0; pp < 16; pp++) {
        int row = (tid >> 5) + pp * 8;
        int c4 = (tid & 31) * 4;
        int gr = r0 + row;
        float4 v = make_float4(0.f, 0.f, 0.f, 0.f);
        if (gr < N) v = *(const float4*)(A + (size_t)gr * K + c4);
        uint32_t u0, u1, u2, u3;
        TF32(u0, v.x); TF32(u1, v.y); TF32(u2, v.z); TF32(u3, v.w);
        AsT[(c4 + 0) * APAD + row] = __uint_as_float(u0);
        AsT[(c4 + 1) * APAD + row] = __uint_as_float(u1);
        AsT[(c4 + 2) * APAD + row] = __uint_as_float(u2);
        AsT[(c4 + 3) * APAD + row] = __uint_as_float(u3);
    }
    __syncthreads();

    float acc[2][4][4];
    #pragma unroll
    for (int m = 0; m < 2; m++)
        #pragma unroll
        for (int j = 0; j < 4; j++)
            #pragma unroll
            for (int q = 0; q < 4; q++) acc[m][j][q] = 0.f;

    #pragma unroll
    for (int kc = 0; kc < K / 8; kc++) {
        const int kl = kc * 8;
        uint32_t bf[4][2];
        #pragma unroll
        for (int j = 0; j < 4; j++) {
            int n = warpN * 32 + j * 8 + g;
            bf[j][0] = __float_as_uint(Ws[(kl + tig) * WPAD + n]);
            bf[j][1] = __float_as_uint(Ws[(kl + tig + 4) * WPAD + n]);
        }
        #pragma unroll
        for (int m = 0; m < 2; m++) {
            int rb = warpM * 32 + m * 16;
            uint32_t a0 = __float_as_uint(AsT[(kl + tig) * APAD + rb + g]);
            uint32_t a1 = __float_as_uint(AsT[(kl + tig) * APAD + rb + g + 8]);
            uint32_t a2 = __float_as_uint(AsT[(kl + tig + 4) * APAD + rb + g]);
            uint32_t a3 = __float_as_uint(AsT[(kl + tig + 4) * APAD + rb + g + 8]);
            #pragma unroll
            for (int j = 0; j < 4; j++)
                MMA_TF32(acc[m][j], a0, a1, a2, a3, bf[j][0], bf[j][1]);
        }
    }

    const float ep = 1.0f + eps_ptr[0];
    #pragma unroll
    for (int m = 0; m < 2; m++) {
        #pragma unroll
        for (int half = 0; half < 2; half++) {
            int gr = r0 + warpM * 32 + m * 16 + g + half * 8;
            if (gr < N) {
                #pragma unroll
                for (int j = 0; j < 4; j++) {
                    int col = warpN * 32 + j * 8 + 2 * tig;
                    float v0 = acc[m][j][half * 2 + 0];
                    float v1 = acc[m][j][half * 2 + 1];
                    *(float2*)(z + (size_t)gr * HDIM + col) =
                        make_float2(v0 * ep, v1 * ep);
                    *(__half2*)(y16 + (size_t)gr * HDIM + col) =
                        __float22half2_rn(make_float2(v0, v1));
                }
            }
        }
    }
}

// ===========================================================================
// Scatter: z[dst] += w * y16[src]  (fp16 gather, fp32 vector red atomics).
// ===========================================================================
__global__ __launch_bounds__(256) void scatter_kernel(
    const int* __restrict__ src, const int* __restrict__ dst,
    const float* __restrict__ ew, const __half* __restrict__ y16,
    float* __restrict__ z, int E)
{
    __shared__ int s_src[64], s_dst[64];
    __shared__ float s_w[64];
    const int base = blockIdx.x * 64;
    const int tid = threadIdx.x;
    if (tid < 64) {
        int e = base + tid;
        if (e < E) { s_src[tid] = src[e]; s_dst[tid] = dst[e]; s_w[tid] = ew[e]; }
    }
    __syncthreads();
    #pragma unroll
    for (int it = 0; it < 4; it++) {
        int idx = it * 256 + tid;
        int e = idx >> 4;
        int c = idx & 15;
        if (base + e < E) {
            float w = s_w[e];
            uint2 hv = *(const uint2*)(y16 + (size_t)s_src[e] * HDIM + c * 4);
            float2 f0 = __half22float2(*(__half2*)&hv.x);
            float2 f1 = __half22float2(*(__half2*)&hv.y);
            float4* p = (float4*)z + (size_t)s_dst[e] * 16 + c;
            asm volatile("red.global.add.v4.f32 [%0], {%1,%2,%3,%4};"
                         :: "l"(p), "f"(w * f0.x), "f"(w * f0.y),
                            "f"(w * f1.x), "f"(w * f1.y)
                         : "memory");
        }
    }
}

// ===========================================================================
// GEMM B (tf32 MMA): h2 = relu(z + ba) @ W + bb, BN stats into stat_set.
// Single-phase staging; shuffle-reduced stats epilogue (R15-proven).
// ===========================================================================
__global__ __launch_bounds__(256) void gemm_b_mma_kernel(
    const float* __restrict__ Zin, const float* __restrict__ W,
    const float* __restrict__ ba, const float* __restrict__ bb,
    float* __restrict__ h2, int N, int stat_set)
{
    constexpr int K = 64, BM = 128;
    extern __shared__ __align__(16) float sm[];
    float* Ws  = sm;
    float* AsT = sm + K * WPAD;
    __shared__ float s_sum[HDIM], s_ssq[HDIM], s_bias[HDIM], s_ba[HDIM];

    const int tid = threadIdx.x;
    const int lane = tid & 31, wid = tid >> 5;
    const int g = lane >> 2, tig = lane & 3;
    const int warpM = wid & 3, warpN = wid >> 2;
    const int r0 = blockIdx.x * BM;

    if (tid < HDIM) {
        s_sum[tid] = 0.f; s_ssq[tid] = 0.f;
        s_bias[tid] = bb[tid];
        s_ba[tid] = ba[tid];
    }
    __syncthreads();                 // s_ba ready for staging math

    #pragma unroll
    for (int i = tid; i < K * 16; i += 256) {
        int row = i >> 4, c4 = (i & 15) * 4;
        float4 v = *(const float4*)(W + (size_t)row * HDIM + c4);
        uint32_t u0, u1, u2, u3;
        TF32(u0, v.x); TF32(u1, v.y); TF32(u2, v.z); TF32(u3, v.w);
        *(float4*)&Ws[row * WPAD + c4] =
            make_float4(__uint_as_float(u0), __uint_as_float(u1),
                        __uint_as_float(u2), __uint_as_float(u3));
    }

    #pragma unroll
    for (int pp = 0; pp < 8; pp++) {
        int row = (tid >> 4) + pp * 16;
        int c4 = (tid & 15) * 4;
        int gr = r0 + row;
        float4 v = make_float4(0.f, 0.f, 0.f, 0.f);
        if (gr < N) {
            v = *(const float4*)(Zin + (size_t)gr * K + c4);
            float4 b = *(const float4*)&s_ba[c4];
            v.x = fmaxf(v.x + b.x, 0.f);
            v.y = fmaxf(v.y + b.y, 0.f);
            v.z = fmaxf(v.z + b.z, 0.f);
            v.w = fmaxf(v.w + b.w, 0.f);
        }
        uint32_t u0, u1, u2, u3;
        TF32(u0, v.x); TF32(u1, v.y); TF32(u2, v.z); TF32(u3, v.w);
        AsT[(c4 + 0) * APAD + row] = __uint_as_float(u0);
        AsT[(c4 + 1) * APAD + row] = __uint_as_float(u1);
        AsT[(c4 + 2) * APAD + row] = __uint_as_float(u2);
        AsT[(c4 + 3) * APAD + row] = __uint_as_float(u3);
    }
    __syncthreads();

    float acc[2][4][4];
    #pragma unroll
    for (int m = 0; m < 2; m++)
        #pragma unroll
        for (int j = 0; j < 4; j++)
            #pragma unroll
            for (int q = 0; q < 4; q++) acc[m][j][q] = 0.f;

    #pragma unroll
    for (int kc = 0; kc < K / 8; kc++) {
        const int kl = kc * 8;
        uint32_t bf[4][2];
        #pragma unroll
        for (int j = 0; j < 4; j++) {
            int n = warpN * 32 + j * 8 + g;
            bf[j][0] = __float_as_uint(Ws[(kl + tig) * WPAD + n]);
            bf[j][1] = __float_as_uint(Ws[(kl + tig + 4) * WPAD + n]);
        }
        #pragma unroll
        for (int m = 0; m < 2; m++) {
            int rb = warpM * 32 + m * 16;
            uint32_t a0 = __float_as_uint(AsT[(kl + tig) * APAD + rb + g]);
            uint32_t a1 = __float_as_uint(AsT[(kl + tig) * APAD + rb + g + 8]);
            uint32_t a2 = __float_as_uint(AsT[(kl + tig + 4) * APAD + rb + g]);
            uint32_t a3 = __float_as_uint(AsT[(kl + tig + 4) * APAD + rb + g + 8]);
            #pragma unroll
            for (int j = 0; j < 4; j++)
                MMA_TF32(acc[m][j], a0, a1, a2, a3, bf[j][0], bf[j][1]);
        }
    }

    float csum[4][2], cssq[4][2];
    #pragma unroll
    for (int j = 0; j < 4; j++)
        #pragma unroll
        for (int q = 0; q < 2; q++) { csum[j][q] = 0.f; cssq[j][q] = 0.f; }

    #pragma unroll
    for (int m = 0; m < 2; m++) {
        #pragma unroll
        for (int half = 0; half < 2; half++) {
            int gr = r0 + warpM * 32 + m * 16 + g + half * 8;
            if (gr < N) {
                #pragma unroll
                for (int j = 0; j < 4; j++) {
                    int col = warpN * 32 + j * 8 + 2 * tig;
                    float v0 = acc[m][j][half * 2 + 0] + s_bias[col];
                    float v1 = acc[m][j][half * 2 + 1] + s_bias[col + 1];
                    *(float2*)(h2 + (size_t)gr * HDIM + col) = make_float2(v0, v1);
                    csum[j][0] += v0; cssq[j][0] += v0 * v0;
                    csum[j][1] += v1; cssq[j][1] += v1 * v1;
                }
            }
        }
    }

    const unsigned FULL = 0xFFFFFFFFu;
    #pragma unroll
    for (int j = 0; j < 4; j++) {
        #pragma unroll
        for (int q = 0; q < 2; q++) {
            float s  = csum[j][q];
            float ss = cssq[j][q];
            s  += __shfl_xor_sync(FULL, s, 4);
            s  += __shfl_xor_sync(FULL, s, 8);
            s  += __shfl_xor_sync(FULL, s, 16);
            ss += __shfl_xor_sync(FULL, ss, 4);
            ss += __shfl_xor_sync(FULL, ss, 8);
            ss += __shfl_xor_sync(FULL, ss, 16);
            if (g == 0) {
                int col = warpN * 32 + j * 8 + 2 * tig + q;
                atomicAdd(&s_sum[col], s);
                atomicAdd(&s_ssq[col], ss);
            }
        }
    }
    __syncthreads();
    if (tid < HDIM) {
        atomicAdd(&g_sum[stat_set][tid], s_sum[tid]);
        atomicAdd(&g_sumsq[stat_set][tid], s_ssq[tid]);
    }
}

// ---------------------------------------------------------------------------
// Final BN apply + residual into d_out.
// ---------------------------------------------------------------------------
__global__ __launch_bounds__(256) void bn_apply_final_kernel(
    const float* __restrict__ h2, const float* __restrict__ hprev,
    float* __restrict__ out,
    const float* __restrict__ gamma, const float* __restrict__ beta,
    int stat_set, float invN, int N)
{
    __shared__ __align__(16) float s_scale[HDIM], s_shift[HDIM];
    const int tid = threadIdx.x;
    if (tid < HDIM) {
        float mean = g_sum[stat_set][tid] * invN;
        float var  = g_sumsq[stat_set][tid] * invN - mean * mean;
        float sc   = gamma[tid] * rsqrtf(var + BN_EPS);
        s_scale[tid] = sc;
        s_shift[tid] = beta[tid] - mean * sc;
    }
    __syncthreads();
    int idx = blockIdx.x * 256 + tid;
    if (idx >= N * 16) return;
    int c4 = (idx & 15) * 4;
    float4 v = ((const float4*)h2)[idx];
    float4 sc = *(const float4*)&s_scale[c4];
    float4 sh = *(const float4*)&s_shift[c4];
    float4 p = ((const float4*)hprev)[idx];
    v.x = p.x + fmaxf(fmaf(v.x, sc.x, sh.x), 0.f);
    v.y = p.y + fmaxf(fmaf(v.y, sc.y, sh.y), 0.f);
    v.z = p.z + fmaxf(fmaf(v.z, sc.z, sh.z), 0.f);
    v.w = p.w + fmaxf(fmaf(v.w, sc.w, sh.w), 0.f);
    ((float4*)out)[idx] = v;
}

// ---------------------------------------------------------------------------
// Host launcher
// ---------------------------------------------------------------------------
extern "C" void kernel_launch(void* const* d_in, const int* in_sizes, int n_in,
                              void* d_out, int out_size)
{
    const float* x    = (const float*)d_in[0];
    const int* ei     = (const int*)d_in[1];     // int32 (JAX x64 disabled)
    const float* ew   = (const float*)d_in[2];
    const float* eps1 = (const float*)d_in[3];
    const float* W1a  = (const float*)d_in[4];
    const float* b1a  = (const float*)d_in[5];
    const float* W1b  = (const float*)d_in[6];
    const float* b1b  = (const float*)d_in[7];
    const float* g1   = (const float*)d_in[8];
    const float* be1  = (const float*)d_in[9];
    const float* epss = (const float*)d_in[10];
    const float* Wsa  = (const float*)d_in[11];
    const float* bsa  = (const float*)d_in[12];
    const float* Wsb  = (const float*)d_in[13];
    const float* bsb  = (const float*)d_in[14];
    const float* gs   = (const float*)d_in[15];
    const float* bes  = (const float*)d_in[16];

    const int F   = in_sizes[4] / in_sizes[5];   // 128
    const int N   = in_sizes[0] / F;
    const int E   = in_sizes[2];
    const int Lm1 = in_sizes[10];

    const int* src = ei;
    const int* dst = ei + E;

    __half* yb;
    float *zb, *h2b, *hb;
    cudaGetSymbolAddress((void**)&yb,  g_y16);
    cudaGetSymbolAddress((void**)&zb,  g_z);
    cudaGetSymbolAddress((void**)&h2b, g_h2);
    cudaGetSymbolAddress((void**)&hb,  g_h);

    // Opt in to large dynamic smem (idempotent; host-side, not captured)
    cudaFuncSetAttribute(gemm_a_mma_kernel,
                         cudaFuncAttributeMaxDynamicSharedMemorySize, DYN_K64);
    cudaFuncSetAttribute(gemm_b_mma_kernel,
                         cudaFuncAttributeMaxDynamicSharedMemorySize, DYN_K64);
    cudaFuncSetAttribute(gemm_a0_mma_kernel,
                         cudaFuncAttributeMaxDynamicSharedMemorySize, DYN_K128);

    const int gemm_blocks = (N + 127) / 128;
    const int scat_blocks = (E + 63) / 64;
    const int bn_blocks   = (N * 16 + 255) / 256;
    const float invN = 1.0f / (float)N;

    // -------- Layer 0 (K = F = 128): tf32 GEMM-first --------
    gemm_a0_mma_kernel<<<gemm_blocks, 256, DYN_K128>>>(x, W1a, eps1, yb, zb, N);
    scatter_kernel<<<scat_blocks, 256>>>(src, dst, ew, yb, zb, E);
    gemm_b_mma_kernel<<<gemm_blocks, 256, DYN_K64>>>(zb, W1b, b1a, b1b, h2b, N, 0);

    // -------- Hidden layers: tf32 MMA gemm_a (BN fused) + tf32 gemm_b --------
    for (int i = 0; i < Lm1; i++) {
        const float* gam = (i == 0) ? g1  : gs  + (size_t)(i - 1) * HDIM;
        const float* bet = (i == 0) ? be1 : bes + (size_t)(i - 1) * HDIM;
        gemm_a_mma_kernel<<<gemm_blocks, 256, DYN_K64>>>(
            h2b, Wsa + (size_t)i * HDIM * HDIM, epss, i,
            gam, bet, /*stat_set=*/i, /*residual=*/(i > 0), invN,
            hb, yb, zb, N);
        scatter_kernel<<<scat_blocks, 256>>>(src, dst, ew, yb, zb, E);
        gemm_b_mma_kernel<<<gemm_blocks, 256, DYN_K64>>>(
            zb, Wsb + (size_t)i * HDIM * HDIM,
            bsa + (size_t)i * HDIM, bsb + (size_t)i * HDIM,
            h2b, N, /*set*/i + 1);
    }

    // -------- Final BN + residual into d_out --------
    bn_apply_final_kernel<<<bn_blocks, 256>>>(
        h2b, hb, (float*)d_out,
        gs + (size_t)(Lm1 - 1) * HDIM, bes + (size_t)(Lm1 - 1) * HDIM,
        /*stat_set=*/Lm1, invN, N);
}

// round 17
// speedup vs baseline: 1.0755x; 1.0755x over previous
#include <cuda_runtime.h>
#include <cuda_fp16.h>
#include <cstdint>

#define HDIM 64
#define BN_EPS 1e-5f
#define MAXN 131072
#define MAXL 4

// Scratch (device globals — no allocation allowed). 16B-aligned.
__device__ __align__(16) __half g_y16[MAXN * HDIM]; // y = h @ Wa (fp16 gather)
__device__ __align__(16) float g_z[MAXN * HDIM];    // z = (1+eps)*y + scatter
__device__ __align__(16) float g_h2[MAXN * HDIM];   // pre-BN output of MLP
__device__ __align__(16) float g_h[MAXN * HDIM];    // residual stream
__device__ __align__(16) float g_sum[MAXL][HDIM];   // per-layer BN stats
__device__ __align__(16) float g_sumsq[MAXL][HDIM];

// tf32 helpers
#define TF32(u, f) asm("cvt.rna.tf32.f32 %0, %1;" : "=r"(u) : "f"(f))
#define MMA_TF32(d, a0, a1, a2, a3, b0, b1) \
    asm volatile("mma.sync.aligned.m16n8k8.row.col.f32.tf32.tf32.f32 " \
        "{%0,%1,%2,%3}, {%4,%5,%6,%7}, {%8,%9}, {%0,%1,%2,%3};" \
        : "+f"(d[0]), "+f"(d[1]), "+f"(d[2]), "+f"(d[3]) \
        : "r"(a0), "r"(a1), "r"(a2), "r"(a3), "r"(b0), "r"(b1))

#define WPAD 72   // Ws row stride in floats (conflict-free B-frag loads)

// ===========================================================================
// GEMM A (tf32 MMA, K=64, FUSE) — R15-proven two-phase structure, now with
// minBlocksPerSM=4 (forces <=64 regs; R16 measured 60 for this body).
// BM=128, 256 thr (8 warps 4x2), m16n8k8, fp32 accum, BK=32.
// y16 = A' @ W (fp16), z = (1+eps)*(A' @ W) (fp32).
// A' = [residual +] relu(BN(h2)) on the fly, written to hbuf (fp32).
// ===========================================================================
__global__ __launch_bounds__(256, 4) void gemm_a_mma_kernel(
    const float* __restrict__ A, const float* __restrict__ W,
    const float* __restrict__ eps_ptr, int eps_idx,
    const float* __restrict__ gamma, const float* __restrict__ beta,
    int stat_set, int residual, float invN,
    float* __restrict__ hbuf, __half* __restrict__ y16,
    float* __restrict__ z, int N)
{
    constexpr int K = 64, BM = 128, BK = 32;
    __shared__ __align__(16) float Ws[K][WPAD];
    __shared__ __align__(16) float AsT[BK][BM + 4];
    __shared__ __align__(16) float s_scale[HDIM], s_shift[HDIM];

    const int tid = threadIdx.x;
    const int lane = tid & 31, wid = tid >> 5;
    const int g = lane >> 2, tig = lane & 3;
    const int warpM = wid & 3, warpN = wid >> 2;
    const int r0 = blockIdx.x * BM;

    if (tid < HDIM) {
        float mean = g_sum[stat_set][tid] * invN;
        float var  = g_sumsq[stat_set][tid] * invN - mean * mean;
        float sc   = gamma[tid] * rsqrtf(var + BN_EPS);
        s_scale[tid] = sc;
        s_shift[tid] = beta[tid] - mean * sc;
    }

    {   // stage W, tf32-rounded, padded rows
        #pragma unroll
        for (int i = tid; i < K * 16; i += 256) {
            int row = i >> 4, c4 = (i & 15) * 4;
            float4 v = *(const float4*)(W + (size_t)row * HDIM + c4);
            uint32_t u0, u1, u2, u3;
            TF32(u0, v.x); TF32(u1, v.y); TF32(u2, v.z); TF32(u3, v.w);
            *(float4*)&Ws[row][c4] =
                make_float4(__uint_as_float(u0), __uint_as_float(u1),
                            __uint_as_float(u2), __uint_as_float(u3));
        }
    }

    float acc[2][4][4];
    #pragma unroll
    for (int m = 0; m < 2; m++)
        #pragma unroll
        for (int j = 0; j < 4; j++)
            #pragma unroll
            for (int q = 0; q < 4; q++) acc[m][j][q] = 0.f;

    constexpr int LPI = BK / 8;
    constexpr int RG  = BK / 4;
    for (int kk = 0; kk < K; kk += BK) {
        __syncthreads();                 // covers s_scale/Ws init on first trip
        #pragma unroll
        for (int pp = 0; pp < LPI; pp++) {
            int row = (tid / RG) + pp * (256 / RG);
            int c4 = (tid % RG) * 4;
            int gr = r0 + row;
            float4 v = make_float4(0.f, 0.f, 0.f, 0.f);
            if (gr < N) {
                v = *(const float4*)(A + (size_t)gr * K + kk + c4);
                float4 sc = *(const float4*)&s_scale[kk + c4];
                float4 sh = *(const float4*)&s_shift[kk + c4];
                v.x = fmaxf(fmaf(v.x, sc.x, sh.x), 0.f);
                v.y = fmaxf(fmaf(v.y, sc.y, sh.y), 0.f);
                v.z = fmaxf(fmaf(v.z, sc.z, sh.z), 0.f);
                v.w = fmaxf(fmaf(v.w, sc.w, sh.w), 0.f);
                float* hp = hbuf + (size_t)gr * K + kk + c4;
                if (residual) {
                    float4 h = *(const float4*)hp;
                    v.x += h.x; v.y += h.y; v.z += h.z; v.w += h.w;
                }
                *(float4*)hp = v;        // full fp32 residual stream
            }
            uint32_t u0, u1, u2, u3;
            TF32(u0, v.x); TF32(u1, v.y); TF32(u2, v.z); TF32(u3, v.w);
            AsT[c4 + 0][row] = __uint_as_float(u0);
            AsT[c4 + 1][row] = __uint_as_float(u1);
            AsT[c4 + 2][row] = __uint_as_float(u2);
            AsT[c4 + 3][row] = __uint_as_float(u3);
        }
        __syncthreads();
        #pragma unroll
        for (int kc = 0; kc < BK / 8; kc++) {
            const int kl = kc * 8;
            uint32_t bf[4][2];
            #pragma unroll
            for (int j = 0; j < 4; j++) {
                int n = warpN * 32 + j * 8 + g;
                bf[j][0] = __float_as_uint(Ws[kk + kl + tig][n]);
                bf[j][1] = __float_as_uint(Ws[kk + kl + tig + 4][n]);
            }
            #pragma unroll
            for (int m = 0; m < 2; m++) {
                int rb = warpM * 32 + m * 16;
                uint32_t a0 = __float_as_uint(AsT[kl + tig][rb + g]);
                uint32_t a1 = __float_as_uint(AsT[kl + tig][rb + g + 8]);
                uint32_t a2 = __float_as_uint(AsT[kl + tig + 4][rb + g]);
                uint32_t a3 = __float_as_uint(AsT[kl + tig + 4][rb + g + 8]);
                #pragma unroll
                for (int j = 0; j < 4; j++)
                    MMA_TF32(acc[m][j], a0, a1, a2, a3, bf[j][0], bf[j][1]);
            }
        }
    }

    const float ep = 1.0f + eps_ptr[eps_idx];
    #pragma unroll
    for (int m = 0; m < 2; m++) {
        #pragma unroll
        for (int half = 0; half < 2; half++) {
            int gr = r0 + warpM * 32 + m * 16 + g + half * 8;
            if (gr < N) {
                #pragma unroll
                for (int j = 0; j < 4; j++) {
                    int col = warpN * 32 + j * 8 + 2 * tig;
                    float v0 = acc[m][j][half * 2 + 0];
                    float v1 = acc[m][j][half * 2 + 1];
                    *(float2*)(z + (size_t)gr * HDIM + col) =
                        make_float2(v0 * ep, v1 * ep);
                    *(__half2*)(y16 + (size_t)gr * HDIM + col) =
                        __float22half2_rn(make_float2(v0, v1));
                }
            }
        }
    }
}

// ===========================================================================
// GEMM A layer-0 (tf32 MMA, K=128, no FUSE): R15 two-phase, BK=16.
// Smem 45.3K < 48K. Block 0 zeroes BN stat sets. (Left at default bounds.)
// ===========================================================================
__global__ __launch_bounds__(256) void gemm_a0_mma_kernel(
    const float* __restrict__ A, const float* __restrict__ W,
    const float* __restrict__ eps_ptr,
    __half* __restrict__ y16, float* __restrict__ z, int N)
{
    constexpr int K = 128, BM = 128, BK = 16;
    __shared__ __align__(16) float Ws[K][WPAD];
    __shared__ __align__(16) float AsT[BK][BM + 4];

    const int tid = threadIdx.x;
    const int lane = tid & 31, wid = tid >> 5;
    const int g = lane >> 2, tig = lane & 3;
    const int warpM = wid & 3, warpN = wid >> 2;
    const int r0 = blockIdx.x * BM;

    if (blockIdx.x == 0 && tid < HDIM) {
        #pragma unroll
        for (int s = 0; s < MAXL; s++) { g_sum[s][tid] = 0.f; g_sumsq[s][tid] = 0.f; }
    }

    {
        #pragma unroll
        for (int i = tid; i < K * 16; i += 256) {
            int row = i >> 4, c4 = (i & 15) * 4;
            float4 v = *(const float4*)(W + (size_t)row * HDIM + c4);
            uint32_t u0, u1, u2, u3;
            TF32(u0, v.x); TF32(u1, v.y); TF32(u2, v.z); TF32(u3, v.w);
            *(float4*)&Ws[row][c4] =
                make_float4(__uint_as_float(u0), __uint_as_float(u1),
                            __uint_as_float(u2), __uint_as_float(u3));
        }
    }

    float acc[2][4][4];
    #pragma unroll
    for (int m = 0; m < 2; m++)
        #pragma unroll
        for (int j = 0; j < 4; j++)
            #pragma unroll
            for (int q = 0; q < 4; q++) acc[m][j][q] = 0.f;

    constexpr int LPI = BK / 8;          // 2
    constexpr int RG  = BK / 4;          // 4
    for (int kk = 0; kk < K; kk += BK) {
        __syncthreads();
        #pragma unroll
        for (int pp = 0; pp < LPI; pp++) {
            int row = (tid / RG) + pp * (256 / RG);
            int c4 = (tid % RG) * 4;
            int gr = r0 + row;
            float4 v = make_float4(0.f, 0.f, 0.f, 0.f);
            if (gr < N) v = *(const float4*)(A + (size_t)gr * K + kk + c4);
            uint32_t u0, u1, u2, u3;
            TF32(u0, v.x); TF32(u1, v.y); TF32(u2, v.z); TF32(u3, v.w);
            AsT[c4 + 0][row] = __uint_as_float(u0);
            AsT[c4 + 1][row] = __uint_as_float(u1);
            AsT[c4 + 2][row] = __uint_as_float(u2);
            AsT[c4 + 3][row] = __uint_as_float(u3);
        }
        __syncthreads();
        #pragma unroll
        for (int kc = 0; kc < BK / 8; kc++) {
            const int kl = kc * 8;
            uint32_t bf[4][2];
            #pragma unroll
            for (int j = 0; j < 4; j++) {
                int n = warpN * 32 + j * 8 + g;
                bf[j][0] = __float_as_uint(Ws[kk + kl + tig][n]);
                bf[j][1] = __float_as_uint(Ws[kk + kl + tig + 4][n]);
            }
            #pragma unroll
            for (int m = 0; m < 2; m++) {
                int rb = warpM * 32 + m * 16;
                uint32_t a0 = __float_as_uint(AsT[kl + tig][rb + g]);
                uint32_t a1 = __float_as_uint(AsT[kl + tig][rb + g + 8]);
                uint32_t a2 = __float_as_uint(AsT[kl + tig + 4][rb + g]);
                uint32_t a3 = __float_as_uint(AsT[kl + tig + 4][rb + g + 8]);
                #pragma unroll
                for (int j = 0; j < 4; j++)
                    MMA_TF32(acc[m][j], a0, a1, a2, a3, bf[j][0], bf[j][1]);
            }
        }
    }

    const float ep = 1.0f + eps_ptr[0];
    #pragma unroll
    for (int m = 0; m < 2; m++) {
        #pragma unroll
        for (int half = 0; half < 2; half++) {
            int gr = r0 + warpM * 32 + m * 16 + g + half * 8;
            if (gr < N) {
                #pragma unroll
                for (int j = 0; j < 4; j++) {
                    int col = warpN * 32 + j * 8 + 2 * tig;
                    float v0 = acc[m][j][half * 2 + 0];
                    float v1 = acc[m][j][half * 2 + 1];
                    *(float2*)(z + (size_t)gr * HDIM + col) =
                        make_float2(v0 * ep, v1 * ep);
                    *(__half2*)(y16 + (size_t)gr * HDIM + col) =
                        __float22half2_rn(make_float2(v0, v1));
                }
            }
        }
    }
}

// ===========================================================================
// Scatter: z[dst] += w * y16[src]  (fp16 gather, fp32 vector red atomics).
// ===========================================================================
__global__ __launch_bounds__(256) void scatter_kernel(
    const int* __restrict__ src, const int* __restrict__ dst,
    const float* __restrict__ ew, const __half* __restrict__ y16,
    float* __restrict__ z, int E)
{
    __shared__ int s_src[64], s_dst[64];
    __shared__ float s_w[64];
    const int base = blockIdx.x * 64;
    const int tid = threadIdx.x;
    if (tid < 64) {
        int e = base + tid;
        if (e < E) { s_src[tid] = src[e]; s_dst[tid] = dst[e]; s_w[tid] = ew[e]; }
    }
    __syncthreads();
    #pragma unroll
    for (int it = 0; it < 4; it++) {
        int idx = it * 256 + tid;
        int e = idx >> 4;
        int c = idx & 15;
        if (base + e < E) {
            float w = s_w[e];
            uint2 hv = *(const uint2*)(y16 + (size_t)s_src[e] * HDIM + c * 4);
            float2 f0 = __half22float2(*(__half2*)&hv.x);
            float2 f1 = __half22float2(*(__half2*)&hv.y);
            float4* p = (float4*)z + (size_t)s_dst[e] * 16 + c;
            asm volatile("red.global.add.v4.f32 [%0], {%1,%2,%3,%4};"
                         :: "l"(p), "f"(w * f0.x), "f"(w * f0.y),
                            "f"(w * f1.x), "f"(w * f1.y)
                         : "memory");
        }
    }
}

// ===========================================================================
// GEMM B (tf32 MMA, R15-proven): h2 = relu(z + ba) @ W + bb, BN stats.
// Shuffle-reduced stats epilogue. minBlocksPerSM=4.
// ===========================================================================
__global__ __launch_bounds__(256, 4) void gemm_b_mma_kernel(
    const float* __restrict__ Zin, const float* __restrict__ W,
    const float* __restrict__ ba, const float* __restrict__ bb,
    float* __restrict__ h2, int N, int stat_set)
{
    constexpr int K = 64, BM = 128, BK = 32;
    __shared__ __align__(16) float Ws[K][WPAD];
    __shared__ __align__(16) float AsT[BK][BM + 4];
    __shared__ float s_sum[HDIM], s_ssq[HDIM], s_bias[HDIM];

    const int tid = threadIdx.x;
    const int lane = tid & 31, wid = tid >> 5;
    const int g = lane >> 2, tig = lane & 3;
    const int warpM = wid & 3, warpN = wid >> 2;
    const int r0 = blockIdx.x * BM;

    if (tid < HDIM) {
        s_sum[tid] = 0.f; s_ssq[tid] = 0.f;
        s_bias[tid] = bb[tid];
    }

    {
        #pragma unroll
        for (int i = tid; i < K * 16; i += 256) {
            int row = i >> 4, c4 = (i & 15) * 4;
            float4 v = *(const float4*)(W + (size_t)row * HDIM + c4);
            uint32_t u0, u1, u2, u3;
            TF32(u0, v.x); TF32(u1, v.y); TF32(u2, v.z); TF32(u3, v.w);
            *(float4*)&Ws[row][c4] =
                make_float4(__uint_as_float(u0), __uint_as_float(u1),
                            __uint_as_float(u2), __uint_as_float(u3));
        }
    }

    float acc[2][4][4];
    #pragma unroll
    for (int m = 0; m < 2; m++)
        #pragma unroll
        for (int j = 0; j < 4; j++)
            #pragma unroll
            for (int q = 0; q < 4; q++) acc[m][j][q] = 0.f;

    constexpr int LPI = BK / 8;
    constexpr int RG  = BK / 4;
    for (int kk = 0; kk < K; kk += BK) {
        __syncthreads();                 // covers s_* init on first trip
        #pragma unroll
        for (int pp = 0; pp < LPI; pp++) {
            int row = (tid / RG) + pp * (256 / RG);
            int c4 = (tid % RG) * 4;
            int gr = r0 + row;
            float4 v = make_float4(0.f, 0.f, 0.f, 0.f);
            if (gr < N) {
                v = *(const float4*)(Zin + (size_t)gr * K + kk + c4);
                float4 b = *(const float4*)(ba + kk + c4);
                v.x = fmaxf(v.x + b.x, 0.f);
                v.y = fmaxf(v.y + b.y, 0.f);
                v.z = fmaxf(v.z + b.z, 0.f);
                v.w = fmaxf(v.w + b.w, 0.f);
            }
            uint32_t u0, u1, u2, u3;
            TF32(u0, v.x); TF32(u1, v.y); TF32(u2, v.z); TF32(u3, v.w);
            AsT[c4 + 0][row] = __uint_as_float(u0);
            AsT[c4 + 1][row] = __uint_as_float(u1);
            AsT[c4 + 2][row] = __uint_as_float(u2);
            AsT[c4 + 3][row] = __uint_as_float(u3);
        }
        __syncthreads();
        #pragma unroll
        for (int kc = 0; kc < BK / 8; kc++) {
            const int kl = kc * 8;
            uint32_t bf[4][2];
            #pragma unroll
            for (int j = 0; j < 4; j++) {
                int n = warpN * 32 + j * 8 + g;
                bf[j][0] = __float_as_uint(Ws[kk + kl + tig][n]);
                bf[j][1] = __float_as_uint(Ws[kk + kl + tig + 4][n]);
            }
            #pragma unroll
            for (int m = 0; m < 2; m++) {
                int rb = warpM * 32 + m * 16;
                uint32_t a0 = __float_as_uint(AsT[kl + tig][rb + g]);
                uint32_t a1 = __float_as_uint(AsT[kl + tig][rb + g + 8]);
                uint32_t a2 = __float_as_uint(AsT[kl + tig + 4][rb + g]);
                uint32_t a3 = __float_as_uint(AsT[kl + tig + 4][rb + g + 8]);
                #pragma unroll
                for (int j = 0; j < 4; j++)
                    MMA_TF32(acc[m][j], a0, a1, a2, a3, bf[j][0], bf[j][1]);
            }
        }
    }

    float csum[4][2], cssq[4][2];
    #pragma unroll
    for (int j = 0; j < 4; j++)
        #pragma unroll
        for (int q = 0; q < 2; q++) { csum[j][q] = 0.f; cssq[j][q] = 0.f; }

    #pragma unroll
    for (int m = 0; m < 2; m++) {
        #pragma unroll
        for (int half = 0; half < 2; half++) {
            int gr = r0 + warpM * 32 + m * 16 + g + half * 8;
            if (gr < N) {
                #pragma unroll
                for (int j = 0; j < 4; j++) {
                    int col = warpN * 32 + j * 8 + 2 * tig;
                    float v0 = acc[m][j][half * 2 + 0] + s_bias[col];
                    float v1 = acc[m][j][half * 2 + 1] + s_bias[col + 1];
                    *(float2*)(h2 + (size_t)gr * HDIM + col) = make_float2(v0, v1);
                    csum[j][0] += v0; cssq[j][0] += v0 * v0;
                    csum[j][1] += v1; cssq[j][1] += v1 * v1;
                }
            }
        }
    }

    const unsigned FULL = 0xFFFFFFFFu;
    #pragma unroll
    for (int j = 0; j < 4; j++) {
        #pragma unroll
        for (int q = 0; q < 2; q++) {
            float s  = csum[j][q];
            float ss = cssq[j][q];
            s  += __shfl_xor_sync(FULL, s, 4);
            s  += __shfl_xor_sync(FULL, s, 8);
            s  += __shfl_xor_sync(FULL, s, 16);
            ss += __shfl_xor_sync(FULL, ss, 4);
            ss += __shfl_xor_sync(FULL, ss, 8);
            ss += __shfl_xor_sync(FULL, ss, 16);
            if (g == 0) {
                int col = warpN * 32 + j * 8 + 2 * tig + q;
                atomicAdd(&s_sum[col], s);
                atomicAdd(&s_ssq[col], ss);
            }
        }
    }
    __syncthreads();
    if (tid < HDIM) {
        atomicAdd(&g_sum[stat_set][tid], s_sum[tid]);
        atomicAdd(&g_sumsq[stat_set][tid], s_ssq[tid]);
    }
}

// ---------------------------------------------------------------------------
// Final BN apply + residual into d_out.
// ---------------------------------------------------------------------------
__global__ __launch_bounds__(256) void bn_apply_final_kernel(
    const float* __restrict__ h2, const float* __restrict__ hprev,
    float* __restrict__ out,
    const float* __restrict__ gamma, const float* __restrict__ beta,
    int stat_set, float invN, int N)
{
    __shared__ __align__(16) float s_scale[HDIM], s_shift[HDIM];
    const int tid = threadIdx.x;
    if (tid < HDIM) {
        float mean = g_sum[stat_set][tid] * invN;
        float var  = g_sumsq[stat_set][tid] * invN - mean * mean;
        float sc   = gamma[tid] * rsqrtf(var + BN_EPS);
        s_scale[tid] = sc;
        s_shift[tid] = beta[tid] - mean * sc;
    }
    __syncthreads();
    int idx = blockIdx.x * 256 + tid;
    if (idx >= N * 16) return;
    int c4 = (idx & 15) * 4;
    float4 v = ((const float4*)h2)[idx];
    float4 sc = *(const float4*)&s_scale[c4];
    float4 sh = *(const float4*)&s_shift[c4];
    float4 p = ((const float4*)hprev)[idx];
    v.x = p.x + fmaxf(fmaf(v.x, sc.x, sh.x), 0.f);
    v.y = p.y + fmaxf(fmaf(v.y, sc.y, sh.y), 0.f);
    v.z = p.z + fmaxf(fmaf(v.z, sc.z, sh.z), 0.f);
    v.w = p.w + fmaxf(fmaf(v.w, sc.w, sh.w), 0.f);
    ((float4*)out)[idx] = v;
}

// ---------------------------------------------------------------------------
// Host launcher
// ---------------------------------------------------------------------------
extern "C" void kernel_launch(void* const* d_in, const int* in_sizes, int n_in,
                              void* d_out, int out_size)
{
    const float* x    = (const float*)d_in[0];
    const int* ei     = (const int*)d_in[1];     // int32 (JAX x64 disabled)
    const float* ew   = (const float*)d_in[2];
    const float* eps1 = (const float*)d_in[3];
    const float* W1a  = (const float*)d_in[4];
    const float* b1a  = (const float*)d_in[5];
    const float* W1b  = (const float*)d_in[6];
    const float* b1b  = (const float*)d_in[7];
    const float* g1   = (const float*)d_in[8];
    const float* be1  = (const float*)d_in[9];
    const float* epss = (const float*)d_in[10];
    const float* Wsa  = (const float*)d_in[11];
    const float* bsa  = (const float*)d_in[12];
    const float* Wsb  = (const float*)d_in[13];
    const float* bsb  = (const float*)d_in[14];
    const float* gs   = (const float*)d_in[15];
    const float* bes  = (const float*)d_in[16];

    const int F   = in_sizes[4] / in_sizes[5];   // 128
    const int N   = in_sizes[0] / F;
    const int E   = in_sizes[2];
    const int Lm1 = in_sizes[10];

    const int* src = ei;
    const int* dst = ei + E;

    __half* yb;
    float *zb, *h2b, *hb;
    cudaGetSymbolAddress((void**)&yb,  g_y16);
    cudaGetSymbolAddress((void**)&zb,  g_z);
    cudaGetSymbolAddress((void**)&h2b, g_h2);
    cudaGetSymbolAddress((void**)&hb,  g_h);

    const int gemm_blocks = (N + 127) / 128;
    const int scat_blocks = (E + 63) / 64;
    const int bn_blocks   = (N * 16 + 255) / 256;
    const float invN = 1.0f / (float)N;

    // -------- Layer 0 (K = F = 128): tf32 GEMM-first --------
    gemm_a0_mma_kernel<<<gemm_blocks, 256>>>(x, W1a, eps1, yb, zb, N);
    scatter_kernel<<<scat_blocks, 256>>>(src, dst, ew, yb, zb, E);
    gemm_b_mma_kernel<<<gemm_blocks, 256>>>(zb, W1b, b1a, b1b, h2b, N, /*set*/0);

    // -------- Hidden layers: tf32 MMA gemm_a (BN fused) + tf32 gemm_b --------
    for (int i = 0; i < Lm1; i++) {
        const float* gam = (i == 0) ? g1  : gs  + (size_t)(i - 1) * HDIM;
        const float* bet = (i == 0) ? be1 : bes + (size_t)(i - 1) * HDIM;
        gemm_a_mma_kernel<<<gemm_blocks, 256>>>(
            h2b, Wsa + (size_t)i * HDIM * HDIM, epss, i,
            gam, bet, /*stat_set=*/i, /*residual=*/(i > 0), invN,
            hb, yb, zb, N);
        scatter_kernel<<<scat_blocks, 256>>>(src, dst, ew, yb, zb, E);
        gemm_b_mma_kernel<<<gemm_blocks, 256>>>(
            zb, Wsb + (size_t)i * HDIM * HDIM,
            bsa + (size_t)i * HDIM, bsb + (size_t)i * HDIM,
            h2b, N, /*set*/i + 1);
    }

    // -------- Final BN + residual into d_out --------
    bn_apply_final_kernel<<<bn_blocks, 256>>>(
        h2b, hb, (float*)d_out,
        gs + (size_t)(Lm1 - 1) * HDIM, bes + (size_t)(Lm1 - 1) * HDIM,
        /*stat_set=*/Lm1, invN, N);
}